// round 4
// baseline (speedup 1.0000x reference)
#include <cuda_runtime.h>
#include <cstddef>

#define BB 8
#define TE 2048
#define TD 256
#define HH 128

#define TT 64     // t-tile in score kernel
#define TJ 8      // j-tile in score kernel (one warp per j)
#define WPAD 132  // padded row stride (floats) for Wenc smem tile

#define JT 16     // j-tile in context kernel
#define TC 64     // t-chunk in context kernel

// Scratch for projected tensors (allocation-free per harness rules)
__device__ float g_Wenc[BB * TE * HH];   // 8 MB
__device__ float g_Udec[BB * TD * HH];   // 1 MB

// ---------------------------------------------------------------------------
// MUFU-based exp2 (EX2). ex2.approx: ~2^-22 rel error, saturates cleanly.
// ---------------------------------------------------------------------------
__device__ __forceinline__ float fexp2(float x) {
    float y;
    asm("ex2.approx.ftz.f32 %0, %1;" : "=f"(y) : "f"(x));
    return y;
}

// tanh(x) = 1 - 2/(exp(2x)+1): 2 MUFU ops (EX2 + RCP).
// x>>0 -> e=inf -> 1; x<<0 -> e=0 -> -1. Accurate to ~1e-6.
__device__ __forceinline__ float ftanh(float x) {
    float e = fexp2(x * 2.8853900817779268f);   // exp(2x)
    return 1.0f - __fdividef(2.0f, e + 1.0f);
}

// ---------------------------------------------------------------------------
// K0: out[row,k] = sum_h in[row,h] * W[h,k]   (H=128 square projection)
// 16 rows per block, 256 threads; W staged in two 64-row chunks.
// which==0 -> g_Wenc, which==1 -> g_Udec
// ---------------------------------------------------------------------------
__global__ void proj_kernel(const float* __restrict__ in,
                            const float* __restrict__ Wm,
                            int which) {
    __shared__ float Ws[64 * HH];    // 32 KB
    __shared__ float ins[16 * HH];   // 8 KB
    float* out = which ? g_Udec : g_Wenc;

    int tid = threadIdx.x;                  // 256 threads
    int row0 = blockIdx.x * 16;

    // stage 16 input rows (2048 floats = 512 float4)
    const float4* in4 = (const float4*)(in + (size_t)row0 * HH);
    float4* ins4 = (float4*)ins;
    ins4[tid]       = in4[tid];
    ins4[tid + 256] = in4[tid + 256];

    int k = tid & 127;
    int g = tid >> 7;   // 0..1 -> rows g*8 .. g*8+7

    float acc[8];
#pragma unroll
    for (int i = 0; i < 8; i++) acc[i] = 0.0f;

    for (int hc = 0; hc < HH; hc += 64) {
        __syncthreads();
        const float4* W4 = (const float4*)(Wm + hc * HH);
        float4* Ws4 = (float4*)Ws;
#pragma unroll
        for (int i = 0; i < 8; i++) Ws4[tid + i * 256] = W4[tid + i * 256];
        __syncthreads();

#pragma unroll 4
        for (int h = 0; h < 64; h++) {
            float wv = Ws[h * HH + k];            // lanes: consecutive k, conflict-free
#pragma unroll
            for (int i = 0; i < 8; i++)
                acc[i] += ins[(g * 8 + i) * HH + hc + h] * wv;   // broadcast (FIXED: +hc)
        }
    }

#pragma unroll
    for (int i = 0; i < 8; i++)
        out[(size_t)(row0 + g * 8 + i) * HH + k] = acc[i];
}

// ---------------------------------------------------------------------------
// K1: raw scores s[b,j,t] = sum_k V[k]*tanh(Wenc[b,t,k]+Udec[b,j,k])
// Grid (TE/TT, TD/TJ, B). 256 threads = 8 warps; warp w owns j = jb*TJ + w,
// lanes cover t = lane and lane+32 within a 64-t tile.
// Wenc tile padded to 132 floats/row: float4 reads are bank-conflict-free.
// Writes raw scores into the e-output region (softmaxed in place by K2).
// ---------------------------------------------------------------------------
__global__ void score_kernel(const float* __restrict__ Va,
                             float* __restrict__ e_out) {
    __shared__ float We[TT * WPAD];   // 33 KB
    __shared__ float Ud[TJ * HH];     // 4 KB
    __shared__ float Vs[HH];          // 0.5 KB

    int tid = threadIdx.x;            // 256
    int b  = blockIdx.z;
    int jb = blockIdx.y;
    int tb = blockIdx.x;

    // stage Wenc tile [TT x H] with padded rows
    {
        const float4* src = (const float4*)(g_Wenc + ((size_t)b * TE + tb * TT) * HH);
        float4* We4 = (float4*)We;
#pragma unroll
        for (int i = 0; i < (TT * HH / 4) / 256; i++) {   // 8 iters
            int idx = tid + i * 256;        // float4 index over [TT][32]
            int r = idx >> 5, c = idx & 31;
            We4[r * (WPAD / 4) + c] = src[idx];
        }
    }
    // stage Udec tile [TJ x H]: exactly 256 float4
    {
        const float4* usrc = (const float4*)(g_Udec + ((size_t)b * TD + jb * TJ) * HH);
        ((float4*)Ud)[tid] = usrc[tid];
    }
    if (tid < HH / 4) ((float4*)Vs)[tid] = ((const float4*)Va)[tid];
    __syncthreads();

    int w = tid >> 5;      // warp index = local j
    int lane = tid & 31;

    const float4* urow = (const float4*)(Ud + w * HH);
    const float4* Wr0  = (const float4*)We + (size_t)lane * (WPAD / 4);
    const float4* Wr1  = Wr0 + 32 * (WPAD / 4);
    const float4* V4   = (const float4*)Vs;

    float acc0 = 0.0f, acc1 = 0.0f;
#pragma unroll 8
    for (int k4 = 0; k4 < HH / 4; k4++) {
        float4 vv = V4[k4];
        float4 uu = urow[k4];
        float4 w0 = Wr0[k4];
        float4 w1 = Wr1[k4];
        acc0 += vv.x * ftanh(w0.x + uu.x) + vv.y * ftanh(w0.y + uu.y)
              + vv.z * ftanh(w0.z + uu.z) + vv.w * ftanh(w0.w + uu.w);
        acc1 += vv.x * ftanh(w1.x + uu.x) + vv.y * ftanh(w1.y + uu.y)
              + vv.z * ftanh(w1.z + uu.z) + vv.w * ftanh(w1.w + uu.w);
    }

    int j  = jb * TJ + w;
    int t0 = tb * TT + lane;
    size_t base = ((size_t)b * TD + j) * TE;
    e_out[base + t0]      = acc0;
    e_out[base + t0 + 32] = acc1;
}

// ---------------------------------------------------------------------------
// K2: in-place softmax over the last axis (TE=2048) of e. One block per row.
// ---------------------------------------------------------------------------
__global__ void softmax_kernel(float* __restrict__ e) {
    __shared__ float red[8];
    int row = blockIdx.x;
    float* p = e + (size_t)row * TE;
    int tid = threadIdx.x;   // 256

    float4* p4 = (float4*)p;
    float4 v0 = p4[tid];
    float4 v1 = p4[tid + 256];

    float m = fmaxf(fmaxf(fmaxf(v0.x, v0.y), fmaxf(v0.z, v0.w)),
                    fmaxf(fmaxf(v1.x, v1.y), fmaxf(v1.z, v1.w)));
#pragma unroll
    for (int o = 16; o; o >>= 1) m = fmaxf(m, __shfl_xor_sync(0xffffffffu, m, o));
    if ((tid & 31) == 0) red[tid >> 5] = m;
    __syncthreads();
    m = red[0];
#pragma unroll
    for (int i = 1; i < 8; i++) m = fmaxf(m, red[i]);
    __syncthreads();

    v0.x = __expf(v0.x - m); v0.y = __expf(v0.y - m);
    v0.z = __expf(v0.z - m); v0.w = __expf(v0.w - m);
    v1.x = __expf(v1.x - m); v1.y = __expf(v1.y - m);
    v1.z = __expf(v1.z - m); v1.w = __expf(v1.w - m);

    float s = ((v0.x + v0.y) + (v0.z + v0.w)) + ((v1.x + v1.y) + (v1.z + v1.w));
#pragma unroll
    for (int o = 16; o; o >>= 1) s += __shfl_xor_sync(0xffffffffu, s, o);
    if ((tid & 31) == 0) red[tid >> 5] = s;
    __syncthreads();
    s = red[0];
#pragma unroll
    for (int i = 1; i < 8; i++) s += red[i];

    float inv = __fdividef(1.0f, s);
    v0.x *= inv; v0.y *= inv; v0.z *= inv; v0.w *= inv;
    v1.x *= inv; v1.y *= inv; v1.z *= inv; v1.w *= inv;
    p4[tid]       = v0;
    p4[tid + 256] = v1;
}

// ---------------------------------------------------------------------------
// K3: c[b,j,h] = sum_t e[b,j,t] * enc[b,t,h]
// One block per (b, 16-j tile). enc staged in 64-t chunks (32KB smem).
// Thread: h = tid&127, owns 8 j's (jg = tid>>7 selects which 8).
// ---------------------------------------------------------------------------
__global__ void context_kernel(const float* __restrict__ enc,
                               const float* __restrict__ e,
                               float* __restrict__ c) {
    __shared__ float encs[TC * HH];   // 32 KB
    __shared__ float es[JT * TC];     // 4 KB

    int tid = threadIdx.x;            // 256
    int bj = blockIdx.x;              // 0 .. B*TD/JT-1
    int b  = bj / (TD / JT);
    int jb = bj % (TD / JT);

    int h  = tid & 127;
    int jg = tid >> 7;                // 0..1

    float acc[8];
#pragma unroll
    for (int i = 0; i < 8; i++) acc[i] = 0.0f;

    for (int tc = 0; tc < TE; tc += TC) {
        __syncthreads();
        // stage enc[b, tc:tc+TC, :]  (2048 float4)
        {
            const float4* src = (const float4*)(enc + ((size_t)b * TE + tc) * HH);
            float4* d4 = (float4*)encs;
#pragma unroll
            for (int i = 0; i < 8; i++) d4[tid + i * 256] = src[tid + i * 256];
        }
        // stage e[b, jb*JT + jj, tc:tc+TC]  (256 float4)
        {
            int jj = tid >> 4, c4 = tid & 15;
            ((float4*)es)[tid] =
                ((const float4*)(e + (((size_t)b * TD + jb * JT + jj) * TE + tc)))[c4];
        }
        __syncthreads();

#pragma unroll 4
        for (int t4 = 0; t4 < TC / 4; t4++) {
            float en0 = encs[(t4 * 4 + 0) * HH + h];
            float en1 = encs[(t4 * 4 + 1) * HH + h];
            float en2 = encs[(t4 * 4 + 2) * HH + h];
            float en3 = encs[(t4 * 4 + 3) * HH + h];
#pragma unroll
            for (int i = 0; i < 8; i++) {
                float4 ev = ((const float4*)es)[(jg * 8 + i) * (TC / 4) + t4];
                acc[i] += ev.x * en0 + ev.y * en1 + ev.z * en2 + ev.w * en3;
            }
        }
    }

    int jbase = b * TD + jb * JT + jg * 8;
#pragma unroll
    for (int i = 0; i < 8; i++)
        c[(size_t)(jbase + i) * HH + h] = acc[i];
}

// ---------------------------------------------------------------------------
// Launch: c_outputs [B,TD,H] then e_outputs [B,TD,TE], flattened in order.
// ---------------------------------------------------------------------------
extern "C" void kernel_launch(void* const* d_in, const int* in_sizes, int n_in,
                              void* d_out, int out_size) {
    const float* enc = (const float*)d_in[0];   // [B,TE,H]
    const float* dec = (const float*)d_in[1];   // [B,TD,D]
    const float* Wa  = (const float*)d_in[2];   // [H,H]
    const float* Ua  = (const float*)d_in[3];   // [D,H]
    const float* Va  = (const float*)d_in[4];   // [H,1]

    float* out   = (float*)d_out;
    float* c_out = out;                          // B*TD*H
    float* e_out = out + (size_t)BB * TD * HH;   // B*TD*TE

    proj_kernel<<<BB * TE / 16, 256>>>(enc, Wa, 0);
    proj_kernel<<<BB * TD / 16, 256>>>(dec, Ua, 1);
    score_kernel<<<dim3(TE / TT, TD / TJ, BB), 256>>>(Va, e_out);
    softmax_kernel<<<BB * TD, 256>>>(e_out);
    context_kernel<<<BB * TD / JT, 256>>>(enc, e_out, c_out);
}

// round 5
// speedup vs baseline: 1.2852x; 1.2852x over previous
#include <cuda_runtime.h>
#include <cstddef>

#define BB 8
#define TE 2048
#define TD 256
#define HH 128

#define TT 64     // t-tile in score kernel
#define TJ 8      // j-tile in score kernel (one warp per j)
#define WPAD 132  // padded row stride (floats) for Wenc smem tile

#define JT 16     // j-tile in context kernel
#define TC 64     // t-chunk in context kernel

// Scratch for projected tensors (allocation-free per harness rules)
__device__ float g_Wenc[BB * TE * HH];   // 8 MB
__device__ float g_Udec[BB * TD * HH];   // 1 MB

// ---------------------------------------------------------------------------
// Single-MUFU tanh: HW MUFU.TANH (sm_75+). Max abs err ~5e-4 — fits the
// 1e-3 output gate with margin (error enters scores through a 128-term
// V-weighted sum with |v|~0.125, partially cancelling).
// ---------------------------------------------------------------------------
__device__ __forceinline__ float ftanh(float x) {
    float y;
    asm("tanh.approx.f32 %0, %1;" : "=f"(y) : "f"(x));
    return y;
}

// ---------------------------------------------------------------------------
// K0: out[row,k] = sum_h in[row,h] * W[h,k]   (H=128 square projection)
// 16 rows per block, 256 threads; W staged in two 64-row chunks.
// which==0 -> g_Wenc, which==1 -> g_Udec
// ---------------------------------------------------------------------------
__global__ void proj_kernel(const float* __restrict__ in,
                            const float* __restrict__ Wm,
                            int which) {
    __shared__ float Ws[64 * HH];    // 32 KB
    __shared__ float ins[16 * HH];   // 8 KB
    float* out = which ? g_Udec : g_Wenc;

    int tid = threadIdx.x;                  // 256 threads
    int row0 = blockIdx.x * 16;

    // stage 16 input rows (2048 floats = 512 float4)
    const float4* in4 = (const float4*)(in + (size_t)row0 * HH);
    float4* ins4 = (float4*)ins;
    ins4[tid]       = in4[tid];
    ins4[tid + 256] = in4[tid + 256];

    int k = tid & 127;
    int g = tid >> 7;   // 0..1 -> rows g*8 .. g*8+7

    float acc[8];
#pragma unroll
    for (int i = 0; i < 8; i++) acc[i] = 0.0f;

    for (int hc = 0; hc < HH; hc += 64) {
        __syncthreads();
        const float4* W4 = (const float4*)(Wm + hc * HH);
        float4* Ws4 = (float4*)Ws;
#pragma unroll
        for (int i = 0; i < 8; i++) Ws4[tid + i * 256] = W4[tid + i * 256];
        __syncthreads();

#pragma unroll 4
        for (int h = 0; h < 64; h++) {
            float wv = Ws[h * HH + k];            // lanes: consecutive k, conflict-free
#pragma unroll
            for (int i = 0; i < 8; i++)
                acc[i] += ins[(g * 8 + i) * HH + hc + h] * wv;   // broadcast
        }
    }

#pragma unroll
    for (int i = 0; i < 8; i++)
        out[(size_t)(row0 + g * 8 + i) * HH + k] = acc[i];
}

// ---------------------------------------------------------------------------
// K1: raw scores s[b,j,t] = sum_k V[k]*tanh(Wenc[b,t,k]+Udec[b,j,k])
// Grid (TE/TT, TD/TJ, B). 256 threads = 8 warps; warp w owns j = jb*TJ + w,
// lanes cover t = lane and lane+32 within a 64-t tile.
// Wenc tile padded to 132 floats/row: float4 reads are bank-conflict-free.
// Writes raw scores into the e-output region (softmaxed in place by K2).
// ---------------------------------------------------------------------------
__global__ void score_kernel(const float* __restrict__ Va,
                             float* __restrict__ e_out) {
    __shared__ float We[TT * WPAD];   // 33 KB
    __shared__ float Ud[TJ * HH];     // 4 KB
    __shared__ float Vs[HH];          // 0.5 KB

    int tid = threadIdx.x;            // 256
    int b  = blockIdx.z;
    int jb = blockIdx.y;
    int tb = blockIdx.x;

    // stage Wenc tile [TT x H] with padded rows
    {
        const float4* src = (const float4*)(g_Wenc + ((size_t)b * TE + tb * TT) * HH);
        float4* We4 = (float4*)We;
#pragma unroll
        for (int i = 0; i < (TT * HH / 4) / 256; i++) {   // 8 iters
            int idx = tid + i * 256;        // float4 index over [TT][32]
            int r = idx >> 5, c = idx & 31;
            We4[r * (WPAD / 4) + c] = src[idx];
        }
    }
    // stage Udec tile [TJ x H]: exactly 256 float4
    {
        const float4* usrc = (const float4*)(g_Udec + ((size_t)b * TD + jb * TJ) * HH);
        ((float4*)Ud)[tid] = usrc[tid];
    }
    if (tid < HH / 4) ((float4*)Vs)[tid] = ((const float4*)Va)[tid];
    __syncthreads();

    int w = tid >> 5;      // warp index = local j
    int lane = tid & 31;

    const float4* urow = (const float4*)(Ud + w * HH);
    const float4* Wr0  = (const float4*)We + (size_t)lane * (WPAD / 4);
    const float4* Wr1  = Wr0 + 32 * (WPAD / 4);
    const float4* V4   = (const float4*)Vs;

    float acc0 = 0.0f, acc1 = 0.0f;
#pragma unroll 8
    for (int k4 = 0; k4 < HH / 4; k4++) {
        float4 vv = V4[k4];
        float4 uu = urow[k4];
        float4 w0 = Wr0[k4];
        float4 w1 = Wr1[k4];
        acc0 += vv.x * ftanh(w0.x + uu.x) + vv.y * ftanh(w0.y + uu.y)
              + vv.z * ftanh(w0.z + uu.z) + vv.w * ftanh(w0.w + uu.w);
        acc1 += vv.x * ftanh(w1.x + uu.x) + vv.y * ftanh(w1.y + uu.y)
              + vv.z * ftanh(w1.z + uu.z) + vv.w * ftanh(w1.w + uu.w);
    }

    int j  = jb * TJ + w;
    int t0 = tb * TT + lane;
    size_t base = ((size_t)b * TD + j) * TE;
    e_out[base + t0]      = acc0;
    e_out[base + t0 + 32] = acc1;
}

// ---------------------------------------------------------------------------
// K2: in-place softmax over the last axis (TE=2048) of e. One block per row.
// ---------------------------------------------------------------------------
__global__ void softmax_kernel(float* __restrict__ e) {
    __shared__ float red[8];
    int row = blockIdx.x;
    float* p = e + (size_t)row * TE;
    int tid = threadIdx.x;   // 256

    float4* p4 = (float4*)p;
    float4 v0 = p4[tid];
    float4 v1 = p4[tid + 256];

    float m = fmaxf(fmaxf(fmaxf(v0.x, v0.y), fmaxf(v0.z, v0.w)),
                    fmaxf(fmaxf(v1.x, v1.y), fmaxf(v1.z, v1.w)));
#pragma unroll
    for (int o = 16; o; o >>= 1) m = fmaxf(m, __shfl_xor_sync(0xffffffffu, m, o));
    if ((tid & 31) == 0) red[tid >> 5] = m;
    __syncthreads();
    m = red[0];
#pragma unroll
    for (int i = 1; i < 8; i++) m = fmaxf(m, red[i]);
    __syncthreads();

    v0.x = __expf(v0.x - m); v0.y = __expf(v0.y - m);
    v0.z = __expf(v0.z - m); v0.w = __expf(v0.w - m);
    v1.x = __expf(v1.x - m); v1.y = __expf(v1.y - m);
    v1.z = __expf(v1.z - m); v1.w = __expf(v1.w - m);

    float s = ((v0.x + v0.y) + (v0.z + v0.w)) + ((v1.x + v1.y) + (v1.z + v1.w));
#pragma unroll
    for (int o = 16; o; o >>= 1) s += __shfl_xor_sync(0xffffffffu, s, o);
    if ((tid & 31) == 0) red[tid >> 5] = s;
    __syncthreads();
    s = red[0];
#pragma unroll
    for (int i = 1; i < 8; i++) s += red[i];

    float inv = __fdividef(1.0f, s);
    v0.x *= inv; v0.y *= inv; v0.z *= inv; v0.w *= inv;
    v1.x *= inv; v1.y *= inv; v1.z *= inv; v1.w *= inv;
    p4[tid]       = v0;
    p4[tid + 256] = v1;
}

// ---------------------------------------------------------------------------
// K3: c[b,j,h] = sum_t e[b,j,t] * enc[b,t,h]
// One block per (b, 16-j tile). enc staged in 64-t chunks (32KB smem).
// Thread: h = tid&127, owns 8 j's (jg = tid>>7 selects which 8).
// ---------------------------------------------------------------------------
__global__ void context_kernel(const float* __restrict__ enc,
                               const float* __restrict__ e,
                               float* __restrict__ c) {
    __shared__ float encs[TC * HH];   // 32 KB
    __shared__ float es[JT * TC];     // 4 KB

    int tid = threadIdx.x;            // 256
    int bj = blockIdx.x;              // 0 .. B*TD/JT-1
    int b  = bj / (TD / JT);
    int jb = bj % (TD / JT);

    int h  = tid & 127;
    int jg = tid >> 7;                // 0..1

    float acc[8];
#pragma unroll
    for (int i = 0; i < 8; i++) acc[i] = 0.0f;

    for (int tc = 0; tc < TE; tc += TC) {
        __syncthreads();
        // stage enc[b, tc:tc+TC, :]  (2048 float4)
        {
            const float4* src = (const float4*)(enc + ((size_t)b * TE + tc) * HH);
            float4* d4 = (float4*)encs;
#pragma unroll
            for (int i = 0; i < 8; i++) d4[tid + i * 256] = src[tid + i * 256];
        }
        // stage e[b, jb*JT + jj, tc:tc+TC]  (256 float4)
        {
            int jj = tid >> 4, c4 = tid & 15;
            ((float4*)es)[tid] =
                ((const float4*)(e + (((size_t)b * TD + jb * JT + jj) * TE + tc)))[c4];
        }
        __syncthreads();

#pragma unroll 4
        for (int t4 = 0; t4 < TC / 4; t4++) {
            float en0 = encs[(t4 * 4 + 0) * HH + h];
            float en1 = encs[(t4 * 4 + 1) * HH + h];
            float en2 = encs[(t4 * 4 + 2) * HH + h];
            float en3 = encs[(t4 * 4 + 3) * HH + h];
#pragma unroll
            for (int i = 0; i < 8; i++) {
                float4 ev = ((const float4*)es)[(jg * 8 + i) * (TC / 4) + t4];
                acc[i] += ev.x * en0 + ev.y * en1 + ev.z * en2 + ev.w * en3;
            }
        }
    }

    int jbase = b * TD + jb * JT + jg * 8;
#pragma unroll
    for (int i = 0; i < 8; i++)
        c[(size_t)(jbase + i) * HH + h] = acc[i];
}

// ---------------------------------------------------------------------------
// Launch: c_outputs [B,TD,H] then e_outputs [B,TD,TE], flattened in order.
// ---------------------------------------------------------------------------
extern "C" void kernel_launch(void* const* d_in, const int* in_sizes, int n_in,
                              void* d_out, int out_size) {
    const float* enc = (const float*)d_in[0];   // [B,TE,H]
    const float* dec = (const float*)d_in[1];   // [B,TD,D]
    const float* Wa  = (const float*)d_in[2];   // [H,H]
    const float* Ua  = (const float*)d_in[3];   // [D,H]
    const float* Va  = (const float*)d_in[4];   // [H,1]

    float* out   = (float*)d_out;
    float* c_out = out;                          // B*TD*H
    float* e_out = out + (size_t)BB * TD * HH;   // B*TD*TE

    proj_kernel<<<BB * TE / 16, 256>>>(enc, Wa, 0);
    proj_kernel<<<BB * TD / 16, 256>>>(dec, Ua, 1);
    score_kernel<<<dim3(TE / TT, TD / TJ, BB), 256>>>(Va, e_out);
    softmax_kernel<<<BB * TD, 256>>>(e_out);
    context_kernel<<<BB * TD / JT, 256>>>(enc, e_out, c_out);
}